// round 15
// baseline (speedup 1.0000x reference)
#include <cuda_runtime.h>
#include <cuda_bf16.h>
#include <cstdint>

namespace {
constexpr int NTOK = 256;
constexpr int DIM  = 1024;
}

// ---------------- scratch (static device globals, graph/alloc-safe) --------
__device__ float g_part[24][NTOK * NTOK];     // split-k partials: z = m*8 + s
__device__ double g_loss;                      // zero-init; reset by last loss block
__device__ unsigned long long g_pairs;         // idem
__device__ unsigned g_count;                   // idem
__device__ int g_selIsByte;

// ---------------- helpers ---------------------------------------------------
__device__ __forceinline__ uint32_t smem_u32(const void* p) {
    uint32_t a;
    asm("{ .reg .u64 t; cvta.to.shared.u64 t, %1; cvt.u32.u64 %0, t; }" : "=r"(a) : "l"(p));
    return a;
}
__device__ __forceinline__ void ldsm4(uint32_t* r, uint32_t addr) {
    asm volatile("ldmatrix.sync.aligned.m8n8.x4.shared.b16 {%0,%1,%2,%3}, [%4];"
                 : "=r"(r[0]), "=r"(r[1]), "=r"(r[2]), "=r"(r[3]) : "r"(addr));
}
__device__ __forceinline__ void mma_bf16(float* c, const uint32_t* a, const uint32_t* b) {
    asm volatile("mma.sync.aligned.m16n8k16.row.col.f32.bf16.bf16.f32 "
                 "{%0,%1,%2,%3}, {%4,%5,%6,%7}, {%8,%9}, {%0,%1,%2,%3};"
                 : "+f"(c[0]), "+f"(c[1]), "+f"(c[2]), "+f"(c[3])
                 : "r"(a[0]), "r"(a[1]), "r"(a[2]), "r"(a[3]), "r"(b[0]), "r"(b[1]));
}
// float4 -> packed hi bf16x4 (uint2) and lo bf16x4 (uint2)
__device__ __forceinline__ void split4(const float4 v, uint2& hi, uint2& lo) {
    __nv_bfloat16 h0 = __float2bfloat16_rn(v.x);
    __nv_bfloat16 h1 = __float2bfloat16_rn(v.y);
    __nv_bfloat16 h2 = __float2bfloat16_rn(v.z);
    __nv_bfloat16 h3 = __float2bfloat16_rn(v.w);
    __nv_bfloat162 hA(h0, h1), hB(h2, h3);
    __nv_bfloat162 lA(__float2bfloat16_rn(v.x - __bfloat162float(h0)),
                      __float2bfloat16_rn(v.y - __bfloat162float(h1)));
    __nv_bfloat162 lB(__float2bfloat16_rn(v.z - __bfloat162float(h2)),
                      __float2bfloat16_rn(v.w - __bfloat162float(h3)));
    hi = make_uint2(*(uint32_t*)&hA, *(uint32_t*)&hB);
    lo = make_uint2(*(uint32_t*)&lA, *(uint32_t*)&lB);
}

// ---------------------------------------------------------------------------
// Tensor GEMM with fused fp32 -> bf16 hi/lo conversion in the staging path.
// (unchanged from R12; see comments there)
// ---------------------------------------------------------------------------
__global__ __launch_bounds__(256) void gemm_mma_kernel(const float* __restrict__ f1,
                                                       const float* __restrict__ f2,
                                                       const unsigned char* __restrict__ s1,
                                                       const unsigned char* __restrict__ s2) {
    __shared__ __align__(16) __nv_bfloat16 sAh[128 * 72];
    __shared__ __align__(16) __nv_bfloat16 sAl[128 * 72];
    __shared__ __align__(16) __nv_bfloat16 sBh[64 * 72];
    __shared__ __align__(16) __nv_bfloat16 sBl[64 * 72];

    const int tid = threadIdx.x;
    const int lane = tid & 31;
    const int wid = tid >> 5;

    if (blockIdx.x == 0) {
        // mask_sents dtype sniff: int32 {0,1} has all non-word-aligned bytes 0
        int v = 0;
        if ((tid & 3) != 0) v = (int)s1[tid] | (int)s2[tid];
        const int any = __syncthreads_or(v);
        if (tid == 0) g_selIsByte = (any != 0) ? 1 : 0;
    }

    const int bz = blockIdx.x;
    const int tile = bz & 7;
    const int rt = tile >> 2;
    const int ct = tile & 3;
    const int zz = bz >> 3;
    const int m = zz >> 3;
    const int s = zz & 7;
    const int rbase = rt * 128;
    const int cbase = ct * 64;
    const int k0 = s * 128;

    const float* __restrict__ A = (m == 2) ? f2 : f1;
    const float* __restrict__ B = (m == 1) ? f1 : f2;

    const uint32_t uAh = smem_u32(sAh);
    const uint32_t uAl = smem_u32(sAl);
    const uint32_t uBh = smem_u32(sBh);
    const uint32_t uBl = smem_u32(sBl);

    const int wr = wid >> 1;
    const int wc = wid & 1;
    const int arow = lane & 15;
    const int acol = (lane >> 4) << 3;
    const uint32_t aoff = (uint32_t)(((wr * 32 + arow) * 72 + acol) * 2);
    const int bi = lane & 7;
    const int bq = lane >> 3;
    const uint32_t boff = (uint32_t)(((wc * 32 + ((bq >> 1) << 3) + bi) * 72 + ((bq & 1) << 3)) * 2);

    float C[2][4][4];
#pragma unroll
    for (int mt = 0; mt < 2; mt++)
#pragma unroll
        for (int nt = 0; nt < 4; nt++)
#pragma unroll
            for (int q = 0; q < 4; q++) C[mt][nt][q] = 0.f;

#pragma unroll
    for (int chunk = 0; chunk < 2; chunk++) {
        const int kg = k0 + chunk * 64;
        __syncthreads();
#pragma unroll
        for (int it = 0; it < 4; it++) {
            const int v = tid + it * 256;
            const int r = v >> 3;
            const int q = v & 7;
            const float* gp = &A[(rbase + r) * DIM + kg + q * 8];
            const float4 vx = *(const float4*)gp;
            const float4 vy = *(const float4*)(gp + 4);
            uint2 hx, lx, hy, ly;
            split4(vx, hx, lx);
            split4(vy, hy, ly);
            const int o = r * 72 + q * 8;
            *(uint4*)&sAh[o] = make_uint4(hx.x, hx.y, hy.x, hy.y);
            *(uint4*)&sAl[o] = make_uint4(lx.x, lx.y, ly.x, ly.y);
        }
#pragma unroll
        for (int it = 0; it < 2; it++) {
            const int v = tid + it * 256;
            const int r = v >> 3;
            const int q = v & 7;
            const float* gp = &B[(cbase + r) * DIM + kg + q * 8];
            const float4 vx = *(const float4*)gp;
            const float4 vy = *(const float4*)(gp + 4);
            uint2 hx, lx, hy, ly;
            split4(vx, hx, lx);
            split4(vy, hy, ly);
            const int o = r * 72 + q * 8;
            *(uint4*)&sBh[o] = make_uint4(hx.x, hx.y, hy.x, hy.y);
            *(uint4*)&sBl[o] = make_uint4(lx.x, lx.y, ly.x, ly.y);
        }
        __syncthreads();

#pragma unroll
        for (int kk = 0; kk < 4; kk++) {
            const uint32_t ka = aoff + kk * 32;
            const uint32_t kb = boff + kk * 32;
            uint32_t ah[2][4], al[2][4], bh[8], bl[8];
            ldsm4(ah[0], uAh + ka);
            ldsm4(ah[1], uAh + ka + 16 * 72 * 2);
            ldsm4(al[0], uAl + ka);
            ldsm4(al[1], uAl + ka + 16 * 72 * 2);
            ldsm4(bh,     uBh + kb);
            ldsm4(bh + 4, uBh + kb + 16 * 72 * 2);
            ldsm4(bl,     uBl + kb);
            ldsm4(bl + 4, uBl + kb + 16 * 72 * 2);
#pragma unroll
            for (int mt = 0; mt < 2; mt++)
#pragma unroll
                for (int nt = 0; nt < 4; nt++) {
                    mma_bf16(C[mt][nt], ah[mt], &bh[nt * 2]);
                    mma_bf16(C[mt][nt], ah[mt], &bl[nt * 2]);
                    mma_bf16(C[mt][nt], al[mt], &bh[nt * 2]);
                }
        }
    }

    float* __restrict__ dst = g_part[m * 8 + s];
    const int erow = lane >> 2;
    const int ecol = (lane & 3) * 2;
#pragma unroll
    for (int mt = 0; mt < 2; mt++)
#pragma unroll
        for (int nt = 0; nt < 4; nt++) {
            const int r0 = rbase + wr * 32 + mt * 16 + erow;
            const int cc = cbase + wc * 32 + nt * 8 + ecol;
            *(float2*)&dst[r0 * NTOK + cc] = make_float2(C[mt][nt][0], C[mt][nt][1]);
            *(float2*)&dst[(r0 + 8) * NTOK + cc] = make_float2(C[mt][nt][2], C[mt][nt][3]);
        }
}

// ---------------------------------------------------------------------------
// Loss inner loop — ZERO MUFU version.
// The R13/R14 per-lane EX2 predication saved nothing: a MUFU instruction
// occupies the pipe (rt=8/SMSP) for the whole warp if ANY lane is live, and
// P(all 32 lanes skip) ~ 0.2%. MUFU occupancy (~262K warp EX2 + LG2) was
// ~10us of the 17us kernel. Replace transcendental math entirely:
//   softplus(x) = max(x,0) + log1p(e^-|x|)
//   e^-|x| ~ Schraudolph bit-exp: f = fma(|x|, -2^23*log2e, 127*2^23 - 361007)
//            clamped, float->int, reinterpret. Rel err ~ +-4% (balanced).
//   log1p(e), e in [0,1]: degree-3 poly e*(a + e*(b + c*e)), p(0)=0,
//            |err| <= ~1e-3 abs.
// Far pairs and +-1e30 sentinels give e ~ 0 -> contribute ~0 exactly; no
// correction bookkeeping. Total loss bias ~1e-5..1e-4 rel (tol 1e-3).
// Cost: ~10 issues/pair, 9 on the full-rate FMA pipe, 1 cvt. No setp chains.
// ---------------------------------------------------------------------------
namespace {
constexpr float EXP_K1 = -12102203.2f;    // -2^23 * log2(e)
constexpr float EXP_B1 = 1064992209.0f;   // 127*2^23 - 361007 (minimax shift)
constexpr float EXP_CL = 8388608.0f;      // 2^23: reinterprets to 2^-125 ~ 0
constexpr float LOG_A = 0.98752f;         // ln(1+e) ~ e(A + e(B + C e)), e in [0,1]
constexpr float LOG_B = -0.40915f;
constexpr float LOG_C = 0.11473f;
}

__device__ __forceinline__ void pair_term(float& racc, float& lacc, float x) {
    racc += fmaxf(x, 0.f);
    float f = fmaf(fabsf(x), EXP_K1, EXP_B1);   // FFMA with |x| modifier
    f = fmaxf(f, EXP_CL);
    const float e = __int_as_float((int)f);     // ~ e^-|x|
    const float t = fmaf(e, fmaf(e, LOG_C, LOG_B), LOG_A);
    lacc = fmaf(e, t, lacc);                    // += ~log1p(e^-|x|)
}

template <int NB>
__device__ __forceinline__ float row_loss(const float* __restrict__ sPos,
                                          const float* __restrict__ sNeg,
                                          int Ppad, int kl, int jg) {
    float nr[NB];
#pragma unroll
    for (int u = 0; u < NB; u++) nr[u] = sNeg[kl + u * 32];
    float r0 = 0.f, r1 = 0.f, l0 = 0.f, l1 = 0.f;
    for (int j = jg; j < Ppad; j += 8) {
        const float p = sPos[j];
#pragma unroll
        for (int u = 0; u < NB; u++) {
            const float x = nr[u] - p;
            if (u & 1) pair_term(r1, l1, x);
            else       pair_term(r0, l0, x);
        }
    }
    return (r0 + r1) + (l0 + l1);
}

__global__ __launch_bounds__(256, 7) void loss_kernel(const int* __restrict__ mc,
                                                      const int* __restrict__ m1,
                                                      const int* __restrict__ m2,
                                                      const void* __restrict__ s1p,
                                                      const void* __restrict__ s2p,
                                                      float* __restrict__ out) {
    const int r = blockIdx.x;
    const int t = r >> 8;
    const int i = r & 255;

    const void* selP = (t == 0 || t == 2) ? s1p : s2p;
    int sel;
    if (g_selIsByte) sel = ((const unsigned char*)selP)[i];
    else             sel = ((const int*)selP)[i];

    __shared__ float sPos[256];
    __shared__ float sNeg[256];
    __shared__ int wPos[8];
    __shared__ float sRed[8];

    const int tid = threadIdx.x;
    const int lane = tid & 31;
    const int wid = tid >> 5;

    if (sel) {  // uniform across block
        // fused split-k reduce while loading
        const int mIdx = (t <= 1) ? 0 : (t - 1);
        const int off = (t == 1) ? (tid * 256 + i) : (i * 256 + tid);
        const float* __restrict__ pb = g_part[mIdx * 8];
        float v = 0.f;
#pragma unroll
        for (int sp = 0; sp < 8; sp++) v += pb[sp * 65536 + off];

        int mk;
        if (t == 0)      mk = mc[i * 256 + tid];
        else if (t == 1) mk = mc[tid * 256 + i];
        else if (t == 2) mk = m1[i * 256 + tid];
        else             mk = m2[i * 256 + tid];

        const unsigned bp = __ballot_sync(0xffffffffu, mk != 0);
        if (lane == 0) wPos[wid] = __popc(bp);
        __syncthreads();

        int baseP = 0, P = 0;
#pragma unroll
        for (int w = 0; w < 8; w++) {
            const int c = wPos[w];
            if (w < wid) baseP += c;
            P += c;
        }
        const int N = 256 - P;
        const int baseN = wid * 32 - baseP;
        const unsigned lt = (1u << lane) - 1u;
        if (mk) sPos[baseP + __popc(bp & lt)] = v;
        else    sNeg[baseN + __popc(~bp & lt)] = v;
        __syncthreads();

        if (tid == 0)
            atomicAdd(&g_pairs, (unsigned long long)P * (unsigned long long)N);

        if (P != 0 && N != 0) {  // uniform
            const int Ppad = (P + 31) & ~31;
            const int Npad = (N + 31) & ~31;
            if (tid >= P && tid < Ppad) sPos[tid] = 1e30f;
            if (tid >= N && tid < Npad) sNeg[tid] = -1e30f;
            __syncthreads();

            const int kl = tid & 31;
            const int jg = tid >> 5;
            float total;
            switch (Npad >> 5) {
                case 1: total = row_loss<1>(sPos, sNeg, Ppad, kl, jg); break;
                case 2: total = row_loss<2>(sPos, sNeg, Ppad, kl, jg); break;
                case 3: total = row_loss<3>(sPos, sNeg, Ppad, kl, jg); break;
                case 4: total = row_loss<4>(sPos, sNeg, Ppad, kl, jg); break;
                case 5: total = row_loss<5>(sPos, sNeg, Ppad, kl, jg); break;
                case 6: total = row_loss<6>(sPos, sNeg, Ppad, kl, jg); break;
                case 7: total = row_loss<7>(sPos, sNeg, Ppad, kl, jg); break;
                default: total = row_loss<8>(sPos, sNeg, Ppad, kl, jg); break;
            }

#pragma unroll
            for (int o = 16; o; o >>= 1) total += __shfl_xor_sync(0xffffffffu, total, o);
            if (lane == 0) sRed[wid] = total;
            __syncthreads();
            if (tid == 0) {
                float bs = 0.f;
#pragma unroll
                for (int w = 0; w < 8; w++) bs += sRed[w];
                atomicAdd(&g_loss, (double)bs);
            }
        }
    }

    // Completion protocol: every block arrives; the last one finalizes.
    __threadfence();
    if (tid == 0) {
        const unsigned old = atomicAdd(&g_count, 1u);
        if (old == (unsigned)(gridDim.x - 1)) {
            const unsigned long long p = g_pairs;
            const double l = g_loss;
            out[0] = (float)((p > 0ull) ? (l / (double)p) : l);
            g_loss = 0.0;          // reset for next graph replay
            g_pairs = 0ull;
            g_count = 0u;
            __threadfence();
        }
    }
}

// ---------------------------------------------------------------------------
// Inputs: 0 f1 f32[256,1024]  1 f2 f32[256,1024]  2 mask_cross i32[256,256]
//         3 mask1 i32[256,256] 4 mask2 i32[256,256] 5/6 mask_sents bool[256]
// ---------------------------------------------------------------------------
extern "C" void kernel_launch(void* const* d_in, const int* in_sizes, int n_in,
                              void* d_out, int out_size) {
    const float* f1 = (const float*)d_in[0];
    const float* f2 = (const float*)d_in[1];
    const int* mc = (const int*)d_in[2];
    const int* m1 = (const int*)d_in[3];
    const int* m2 = (const int*)d_in[4];
    const unsigned char* s1 = (const unsigned char*)d_in[5];
    const unsigned char* s2 = (const unsigned char*)d_in[6];

    gemm_mma_kernel<<<192, 256>>>(f1, f2, s1, s2);
    loss_kernel<<<1024, 256>>>(mc, m1, m2, (const void*)s1, (const void*)s2,
                               (float*)d_out);
}